// round 1
// baseline (speedup 1.0000x reference)
#include <cuda_runtime.h>
#include <math.h>

#define TOTN 128000
#define FIN 32
#define HD 64
#define HEADS 4
#define DHD 16
#define NL 4
#define NE 512000
#define NB 128
#define OBSD 1500
#define HSD 512
#define NOUTD 15
#define AD 15
#define VHD 128

// ---------------- scratch (static device globals; no allocation) ----------------
__device__ float g_x[TOTN * HD];
__device__ float g_q[TOTN * HD];
__device__ float g_k[TOTN * HD];
__device__ float g_v[TOTN * HD];
__device__ float g_agg[TOTN * HD];
__device__ float g_denom[TOTN * HEADS];
__device__ float g_gat[NB * AD];
__device__ float g_feat[NB * HSD];
__device__ float g_feat2[NB * HSD];
__device__ float g_vh[NB * VHD];
__device__ float g_vh2[NB * VHD];
__device__ float g_pacc[NB * HSD];

// ---------------- input projection: x = nf @ W_in  [TOT,32]x[32,64] ----------------
__global__ void inproj_kernel(const float* __restrict__ nf, const float* __restrict__ Win) {
    __shared__ float ws[FIN * HD];
    int tid = threadIdx.x;
#pragma unroll
    for (int i = 0; i < 8; i++) ws[tid + i * 256] = Win[tid + i * 256];
    __syncthreads();
    int t = blockIdx.x * 256 + tid;            // t < TOT*64
    int node = t >> 6, col = t & 63;
    const float* nfr = nf + node * FIN;
    float s = 0.f;
#pragma unroll
    for (int k = 0; k < FIN; k++) s += nfr[k] * ws[k * HD + col];
    g_x[t] = s;
}

// ---------------- zero agg/denom ----------------
__global__ void zero_attn_kernel() {
    int idx = blockIdx.x * blockDim.x + threadIdx.x;
    int stride = gridDim.x * blockDim.x;
    for (int i = idx; i < TOTN * HD; i += stride) g_agg[i] = 0.f;
    for (int i = idx; i < TOTN * HEADS; i += stride) g_denom[i] = 0.f;
}

// ---------------- QKV: 64-node tile, 3 fused 64x64 GEMMs ----------------
__global__ void qkv_kernel(const float* __restrict__ Wq, const float* __restrict__ Wk,
                           const float* __restrict__ Wv) {
    __shared__ float xs[64][68];   // x transposed: xs[k][row]
    __shared__ float ws[64 * 64];  // weight, k-major
    int n0 = blockIdx.x * 64;
    int tid = threadIdx.x;
    int ty = tid >> 4, tx = tid & 15;
#pragma unroll
    for (int i = 0; i < 16; i++) {
        int idx = tid + i * 256;
        int r = idx >> 6, k = idx & 63;
        xs[k][r] = g_x[(n0 + r) * HD + k];
    }
#pragma unroll
    for (int m = 0; m < 3; m++) {
        const float* Wm = (m == 0) ? Wq : (m == 1) ? Wk : Wv;
        float* Om = (m == 0) ? g_q : (m == 1) ? g_k : g_v;
        __syncthreads();
#pragma unroll
        for (int i = 0; i < 16; i++) { int idx = tid + i * 256; ws[idx] = Wm[idx]; }
        __syncthreads();
        float acc[4][4] = {};
#pragma unroll
        for (int k = 0; k < 64; k++) {
            float4 av = *(const float4*)&xs[k][ty * 4];
            float4 bv = *(const float4*)&ws[k * 64 + tx * 4];
            float a[4] = {av.x, av.y, av.z, av.w};
            float b[4] = {bv.x, bv.y, bv.z, bv.w};
#pragma unroll
            for (int i = 0; i < 4; i++)
#pragma unroll
                for (int j = 0; j < 4; j++) acc[i][j] += a[i] * b[j];
        }
#pragma unroll
        for (int i = 0; i < 4; i++) {
            float4 o = make_float4(acc[i][0], acc[i][1], acc[i][2], acc[i][3]);
            *(float4*)&Om[(n0 + ty * 4 + i) * HD + tx * 4] = o;
        }
    }
}

// ---------------- edge pass: scores, exp, atomic denom + aggregation ----------------
__global__ void edge_kernel(const int* __restrict__ esrc, const int* __restrict__ edst) {
    int e = blockIdx.x * blockDim.x + threadIdx.x;
    if (e >= NE) return;
    int sN = esrc[e], dN = edst[e];
    const float4* q4 = (const float4*)(g_q + dN * HD);
    const float4* k4 = (const float4*)(g_k + sN * HD);
    float s[4] = {0.f, 0.f, 0.f, 0.f};
#pragma unroll
    for (int i = 0; i < 16; i++) {
        float4 a = q4[i], b = k4[i];
        s[i >> 2] += a.x * b.x + a.y * b.y + a.z * b.z + a.w * b.w;
    }
    float w[4];
#pragma unroll
    for (int h = 0; h < 4; h++) {
        w[h] = expf(s[h] * 0.25f);
        atomicAdd(&g_denom[dN * HEADS + h], w[h]);
    }
    const float4* v4 = (const float4*)(g_v + sN * HD);
    float* aggp = g_agg + dN * HD;
#pragma unroll
    for (int i = 0; i < 16; i++) {
        float4 vv = v4[i];
        float wh = w[i >> 2];
        atomicAdd(&aggp[i * 4 + 0], wh * vv.x);
        atomicAdd(&aggp[i * 4 + 1], wh * vv.y);
        atomicAdd(&aggp[i * 4 + 2], wh * vv.z);
        atomicAdd(&aggp[i * 4 + 3], wh * vv.w);
    }
}

// ---------------- O-proj + residual + LN1 (64-node tile) ----------------
__global__ void oln_kernel(const float* __restrict__ Wo, const float* __restrict__ gam,
                           const float* __restrict__ bet) {
    __shared__ float xs[64][68];   // (agg/denom) transposed
    __shared__ float ws[64 * 64];  // Wo, then reused as C tile
    int n0 = blockIdx.x * 64;
    int tid = threadIdx.x;
    int ty = tid >> 4, tx = tid & 15;
#pragma unroll
    for (int i = 0; i < 16; i++) {
        int idx = tid + i * 256;
        int r = idx >> 6, k = idx & 63;
        float d = g_denom[(n0 + r) * HEADS + (k >> 4)];
        float a = g_agg[(n0 + r) * HD + k];
        xs[k][r] = (d > 0.f) ? a / d : 0.f;
        ws[idx] = Wo[idx];
    }
    __syncthreads();
    float acc[4][4] = {};
#pragma unroll
    for (int k = 0; k < 64; k++) {
        float4 av = *(const float4*)&xs[k][ty * 4];
        float4 bv = *(const float4*)&ws[k * 64 + tx * 4];
        float a[4] = {av.x, av.y, av.z, av.w};
        float b[4] = {bv.x, bv.y, bv.z, bv.w};
#pragma unroll
        for (int i = 0; i < 4; i++)
#pragma unroll
            for (int j = 0; j < 4; j++) acc[i][j] += a[i] * b[j];
    }
    __syncthreads();
#pragma unroll
    for (int i = 0; i < 4; i++)
#pragma unroll
        for (int j = 0; j < 4; j++) ws[(ty * 4 + i) * 64 + tx * 4 + j] = acc[i][j];
    __syncthreads();
    // LN: 4 threads per row
    int r = tid >> 2, p = tid & 3;
    float vals[16];
    float sum = 0.f;
#pragma unroll
    for (int j = 0; j < 16; j++) {
        int c = p * 16 + j;
        float t = ws[r * 64 + c] + g_x[(n0 + r) * HD + c];
        vals[j] = t; sum += t;
    }
    sum += __shfl_xor_sync(0xffffffffu, sum, 1);
    sum += __shfl_xor_sync(0xffffffffu, sum, 2);
    float mean = sum * (1.f / 64.f);
    float vsum = 0.f;
#pragma unroll
    for (int j = 0; j < 16; j++) { float d = vals[j] - mean; vsum += d * d; }
    vsum += __shfl_xor_sync(0xffffffffu, vsum, 1);
    vsum += __shfl_xor_sync(0xffffffffu, vsum, 2);
    float rstd = rsqrtf(vsum * (1.f / 64.f) + 1e-5f);
#pragma unroll
    for (int j = 0; j < 16; j++) {
        int c = p * 16 + j;
        g_x[(n0 + r) * HD + c] = (vals[j] - mean) * rstd * gam[c] + bet[c];
    }
}

// ---------------- FFN (64->128 relu ->64) + residual + LN2 (64-node tile) ----------------
__global__ void ffn_kernel(const float* __restrict__ W1, const float* __restrict__ b1v,
                           const float* __restrict__ W2, const float* __restrict__ b2v,
                           const float* __restrict__ gam, const float* __restrict__ bet) {
    extern __shared__ float smem[];
    float* xs = smem;               // [64][68] x transposed
    float* sw = smem + 64 * 68;     // 8704 floats: W1 (stride 132) / W2 (stride 68) / C (stride 68)
    float* hs = sw + 8704;          // [128][68] hidden transposed
    int n0 = blockIdx.x * 64;
    int tid = threadIdx.x;
    int ty = tid >> 4, tx = tid & 15;
#pragma unroll
    for (int i = 0; i < 16; i++) {
        int idx = tid + i * 256;
        int r = idx >> 6, k = idx & 63;
        xs[k * 68 + r] = g_x[(n0 + r) * HD + k];
    }
#pragma unroll
    for (int i = 0; i < 32; i++) {
        int idx = tid + i * 256;           // < 8192
        int k = idx >> 7, j = idx & 127;
        sw[k * 132 + j] = W1[idx];
    }
    __syncthreads();
    // GEMM1: [64x64] @ [64x128] -> micro 4 rows x 8 cols
    float acc1[4][8] = {};
#pragma unroll
    for (int k = 0; k < 64; k++) {
        float4 av = *(const float4*)&xs[k * 68 + ty * 4];
        float4 b0 = *(const float4*)&sw[k * 132 + tx * 8];
        float4 b1q = *(const float4*)&sw[k * 132 + tx * 8 + 4];
        float a[4] = {av.x, av.y, av.z, av.w};
        float b[8] = {b0.x, b0.y, b0.z, b0.w, b1q.x, b1q.y, b1q.z, b1q.w};
#pragma unroll
        for (int i = 0; i < 4; i++)
#pragma unroll
            for (int j = 0; j < 8; j++) acc1[i][j] += a[i] * b[j];
    }
#pragma unroll
    for (int i = 0; i < 4; i++)
#pragma unroll
        for (int j = 0; j < 8; j++) {
            float h = acc1[i][j] + b1v[tx * 8 + j];
            hs[(tx * 8 + j) * 68 + (ty * 4 + i)] = fmaxf(h, 0.f);
        }
    __syncthreads();
#pragma unroll
    for (int i = 0; i < 32; i++) {
        int idx = tid + i * 256;           // < 8192
        int k = idx >> 6, j = idx & 63;
        sw[k * 68 + j] = W2[idx];
    }
    __syncthreads();
    // GEMM2: [64x128] @ [128x64] -> micro 4x4
    float acc2[4][4] = {};
#pragma unroll
    for (int k = 0; k < 128; k++) {
        float4 av = *(const float4*)&hs[k * 68 + ty * 4];
        float4 bv = *(const float4*)&sw[k * 68 + tx * 4];
        float a[4] = {av.x, av.y, av.z, av.w};
        float b[4] = {bv.x, bv.y, bv.z, bv.w};
#pragma unroll
        for (int i = 0; i < 4; i++)
#pragma unroll
            for (int j = 0; j < 4; j++) acc2[i][j] += a[i] * b[j];
    }
    __syncthreads();
#pragma unroll
    for (int i = 0; i < 4; i++)
#pragma unroll
        for (int j = 0; j < 4; j++)
            sw[(ty * 4 + i) * 68 + tx * 4 + j] = acc2[i][j] + b2v[tx * 4 + j];
    __syncthreads();
    // LN2 with residual from xs
    int r = tid >> 2, p = tid & 3;
    float vals[16];
    float sum = 0.f;
#pragma unroll
    for (int j = 0; j < 16; j++) {
        int c = p * 16 + j;
        float t = sw[r * 68 + c] + xs[c * 68 + r];
        vals[j] = t; sum += t;
    }
    sum += __shfl_xor_sync(0xffffffffu, sum, 1);
    sum += __shfl_xor_sync(0xffffffffu, sum, 2);
    float mean = sum * (1.f / 64.f);
    float vsum = 0.f;
#pragma unroll
    for (int j = 0; j < 16; j++) { float d = vals[j] - mean; vsum += d * d; }
    vsum += __shfl_xor_sync(0xffffffffu, vsum, 1);
    vsum += __shfl_xor_sync(0xffffffffu, vsum, 2);
    float rstd = rsqrtf(vsum * (1.f / 64.f) + 1e-5f);
#pragma unroll
    for (int j = 0; j < 16; j++) {
        int c = p * 16 + j;
        g_x[(n0 + r) * HD + c] = (vals[j] - mean) * rstd * gam[c] + bet[c];
    }
}

// ---------------- readout: gat = x[agent] @ Wr + br ----------------
__global__ void readout_kernel(const int* __restrict__ agent, const float* __restrict__ Wr,
                               const float* __restrict__ br) {
    int t = blockIdx.x * blockDim.x + threadIdx.x;
    if (t >= NB * AD) return;
    int b = t / AD, a = t % AD;
    int node = agent[b];
    float s = br[a];
    const float* xr = g_x + node * HD;
#pragma unroll
    for (int h = 0; h < HD; h++) s += xr[h] * Wr[h * AD + a];
    g_gat[t] = s;
}

// ---------------- small GEMM helpers (M=128) ----------------
__global__ void init_bias_kernel(float* dst, const float* __restrict__ bias, int rows, int cols) {
    int idx = blockIdx.x * blockDim.x + threadIdx.x;
    if (idx < rows * cols) dst[idx] = bias[idx % cols];
}

__global__ void tanh_kernel(float* dst, const float* __restrict__ src, int n) {
    int idx = blockIdx.x * blockDim.x + threadIdx.x;
    if (idx < n) dst[idx] = tanhf(src[idx]);
}

// C_acc += A[128,K] @ W[K,ldw-cols], K split over gridDim.y, 64-col tiles over gridDim.x.
// A(r,k) = k < preLen ? Apre[r*preLd+k] : Amain[r*mainLd + k - preLen]
__global__ void gemm_partial_kernel(const float* __restrict__ Apre, int preLen, int preLd,
                                    const float* __restrict__ Amain, int mainLd,
                                    const float* __restrict__ W, int ldw, int Ktot,
                                    float* Cacc, int ldc) {
    __shared__ float As[32 * 132];  // As[kk][r], r<128
    __shared__ float Ws[32 * 68];   // Ws[kk][j], j<64
    int colBase = blockIdx.x * 64;
    int kchunks = (Ktot + 31) / 32;
    int per = (kchunks + gridDim.y - 1) / gridDim.y;
    int c0 = blockIdx.y * per;
    int c1 = min(c0 + per, kchunks);
    int tid = threadIdx.x;
    int ty = tid >> 4, tx = tid & 15;   // rows ty*8.., cols tx*4..
    float acc[8][4] = {};
    for (int c = c0; c < c1; c++) {
        int kb = c * 32;
        __syncthreads();
#pragma unroll
        for (int i = 0; i < 16; i++) {
            int idx = tid + i * 256;       // < 4096
            int r = idx >> 5, kk = idx & 31;
            int k = kb + kk;
            float vv = 0.f;
            if (k < Ktot)
                vv = (k < preLen) ? Apre[r * preLd + k] : Amain[r * mainLd + k - preLen];
            As[kk * 132 + r] = vv;
        }
#pragma unroll
        for (int i = 0; i < 8; i++) {
            int idx = tid + i * 256;       // < 2048
            int kk = idx >> 6, j = idx & 63;
            int k = kb + kk;
            Ws[kk * 68 + j] = (k < Ktot) ? W[k * ldw + colBase + j] : 0.f;
        }
        __syncthreads();
#pragma unroll
        for (int kk = 0; kk < 32; kk++) {
            float4 a0 = *(const float4*)&As[kk * 132 + ty * 8];
            float4 a1 = *(const float4*)&As[kk * 132 + ty * 8 + 4];
            float4 bv = *(const float4*)&Ws[kk * 68 + tx * 4];
            float a[8] = {a0.x, a0.y, a0.z, a0.w, a1.x, a1.y, a1.z, a1.w};
            float b[4] = {bv.x, bv.y, bv.z, bv.w};
#pragma unroll
            for (int i = 0; i < 8; i++)
#pragma unroll
                for (int j = 0; j < 4; j++) acc[i][j] += a[i] * b[j];
        }
    }
#pragma unroll
    for (int i = 0; i < 8; i++)
#pragma unroll
        for (int j = 0; j < 4; j++)
            atomicAdd(&Cacc[(ty * 8 + i) * ldc + colBase + tx * 4 + j], acc[i][j]);
}

// ---------------- heads ----------------
__global__ void logits_kernel(const float* __restrict__ Wlog, const float* __restrict__ blog,
                              float* out) {
    int t = blockIdx.x * blockDim.x + threadIdx.x;
    if (t >= NB * NOUTD) return;
    int b = t / NOUTD, o = t % NOUTD;
    float s = blog[o];
    const float* fr = g_feat2 + b * HSD;
    for (int k = 0; k < HSD; k++) s += fr[k] * Wlog[k * NOUTD + o];
    out[t] = s;
}

__global__ void value_kernel(const float* __restrict__ Wvo, const float* __restrict__ bvo,
                             float* out) {
    int b = blockIdx.x * blockDim.x + threadIdx.x;
    if (b >= NB) return;
    float s = bvo[0];
    const float* vr = g_vh2 + b * VHD;
#pragma unroll
    for (int k = 0; k < VHD; k++) s += vr[k] * Wvo[k];
    out[NB * NOUTD + b] = s;
}

// ---------------- launch ----------------
extern "C" void kernel_launch(void* const* d_in, const int* in_sizes, int n_in,
                              void* d_out, int out_size) {
    const float* nf     = (const float*)d_in[0];
    const float* obs    = (const float*)d_in[1];
    const int*   esrc   = (const int*)d_in[2];
    const int*   edst   = (const int*)d_in[3];
    const int*   agent  = (const int*)d_in[4];
    const float* Win    = (const float*)d_in[5];
    const float* Wq     = (const float*)d_in[6];
    const float* Wk     = (const float*)d_in[7];
    const float* Wv     = (const float*)d_in[8];
    const float* Wo     = (const float*)d_in[9];
    const float* ln1g   = (const float*)d_in[10];
    const float* ln1b   = (const float*)d_in[11];
    const float* W1     = (const float*)d_in[12];
    const float* b1     = (const float*)d_in[13];
    const float* W2     = (const float*)d_in[14];
    const float* b2     = (const float*)d_in[15];
    const float* ln2g   = (const float*)d_in[16];
    const float* ln2b   = (const float*)d_in[17];
    const float* Wr     = (const float*)d_in[18];
    const float* br     = (const float*)d_in[19];
    const float* Wp1    = (const float*)d_in[20];
    const float* bp1    = (const float*)d_in[21];
    const float* Wp2    = (const float*)d_in[22];
    const float* bp2    = (const float*)d_in[23];
    const float* Wlog   = (const float*)d_in[24];
    const float* blog   = (const float*)d_in[25];
    const float* Wv1    = (const float*)d_in[26];
    const float* bv1    = (const float*)d_in[27];
    const float* Wv2    = (const float*)d_in[28];
    const float* bv2    = (const float*)d_in[29];
    const float* Wvo    = (const float*)d_in[30];
    const float* bvo    = (const float*)d_in[31];
    float* out = (float*)d_out;

    cudaFuncSetAttribute(ffn_kernel, cudaFuncAttributeMaxDynamicSharedMemorySize, 87040);

    float *p_gat, *p_feat, *p_feat2, *p_vh, *p_vh2, *p_pacc;
    cudaGetSymbolAddress((void**)&p_gat, g_gat);
    cudaGetSymbolAddress((void**)&p_feat, g_feat);
    cudaGetSymbolAddress((void**)&p_feat2, g_feat2);
    cudaGetSymbolAddress((void**)&p_vh, g_vh);
    cudaGetSymbolAddress((void**)&p_vh2, g_vh2);
    cudaGetSymbolAddress((void**)&p_pacc, g_pacc);

    inproj_kernel<<<TOTN * HD / 256, 256>>>(nf, Win);

    for (int l = 0; l < NL; l++) {
        zero_attn_kernel<<<4096, 256>>>();
        qkv_kernel<<<TOTN / 64, 256>>>(Wq + l * HD * HD, Wk + l * HD * HD, Wv + l * HD * HD);
        edge_kernel<<<NE / 256, 256>>>(esrc, edst);
        oln_kernel<<<TOTN / 64, 256>>>(Wo + l * HD * HD, ln1g + l * HD, ln1b + l * HD);
        ffn_kernel<<<TOTN / 64, 256, 87040>>>(W1 + l * HD * 2 * HD, b1 + l * 2 * HD,
                                              W2 + l * 2 * HD * HD, b2 + l * HD,
                                              ln2g + l * HD, ln2b + l * HD);
    }

    readout_kernel<<<(NB * AD + 255) / 256, 256>>>(agent, Wr, br);

    // policy head
    init_bias_kernel<<<(NB * HSD + 255) / 256, 256>>>(p_pacc, bp1, NB, HSD);
    gemm_partial_kernel<<<dim3(8, 8), 256>>>(p_gat, AD, AD, obs, OBSD, Wp1, HSD, AD + OBSD,
                                             p_pacc, HSD);
    tanh_kernel<<<(NB * HSD + 255) / 256, 256>>>(p_feat, p_pacc, NB * HSD);

    init_bias_kernel<<<(NB * HSD + 255) / 256, 256>>>(p_pacc, bp2, NB, HSD);
    gemm_partial_kernel<<<dim3(8, 4), 256>>>(nullptr, 0, 0, p_feat, HSD, Wp2, HSD, HSD,
                                             p_pacc, HSD);
    tanh_kernel<<<(NB * HSD + 255) / 256, 256>>>(p_feat2, p_pacc, NB * HSD);

    logits_kernel<<<(NB * NOUTD + 255) / 256, 256>>>(Wlog, blog, out);

    // value head
    init_bias_kernel<<<(NB * VHD + 255) / 256, 256>>>(p_pacc, bv1, NB, VHD);
    gemm_partial_kernel<<<dim3(2, 8), 256>>>(nullptr, 0, 0, obs, OBSD, Wv1, VHD, OBSD,
                                             p_pacc, VHD);
    tanh_kernel<<<(NB * VHD + 255) / 256, 256>>>(p_vh, p_pacc, NB * VHD);

    init_bias_kernel<<<(NB * VHD + 255) / 256, 256>>>(p_pacc, bv2, NB, VHD);
    gemm_partial_kernel<<<dim3(2, 1), 256>>>(nullptr, 0, 0, p_vh, VHD, Wv2, VHD, VHD,
                                             p_pacc, VHD);
    tanh_kernel<<<(NB * VHD + 255) / 256, 256>>>(p_vh2, p_pacc, NB * VHD);

    value_kernel<<<1, NB>>>(Wvo, bvo, out);
}